// round 2
// baseline (speedup 1.0000x reference)
#include <cuda_runtime.h>
#include <cstdint>

// ---------------------------------------------------------------------------
// WindowAttention3D: B=768, N=144, C=512, H=16, hd=32, NW=96
// Round 2: tf32 converted at staging; k-permuted GEMM smem (LDS.64 frags);
//          warp-per-row-tile attention with parallel softmax.
// ---------------------------------------------------------------------------

#define B_TOT   768
#define NTOK    144
#define DIMC    512
#define NH      16
#define HD      32
#define NWIN    96
#define SCALE   0.17677669529663687f   // 1/sqrt(32)
#define NTOK2   (NTOK*NTOK)            // 20736
#define BHSTRIDE (NTOK*HD)             // 4608

// Scratch (device globals; allocation-free rule)
__device__ float g_qkv[3u*768u*16u*144u*32u];   // [3][B][H][N][hd]
__device__ float g_ctx[768u*144u*512u];         // [B][N][C]
__device__ float g_bias[16u*144u*144u];         // [H][N][N]

// ---------------------------------------------------------------------------
__device__ __forceinline__ uint32_t f2tf(float x) {
    uint32_t r;
    asm("cvt.rna.tf32.f32 %0, %1;" : "=r"(r) : "f"(x));
    return r;
}

__device__ __forceinline__ void mma_tf32(float* c, const uint32_t* a, const uint32_t* b) {
    asm volatile(
        "mma.sync.aligned.m16n8k8.row.col.f32.tf32.tf32.f32 "
        "{%0,%1,%2,%3},{%4,%5,%6,%7},{%8,%9},{%0,%1,%2,%3};\n"
        : "+f"(c[0]), "+f"(c[1]), "+f"(c[2]), "+f"(c[3])
        : "r"(a[0]), "r"(a[1]), "r"(a[2]), "r"(a[3]), "r"(b[0]), "r"(b[1]));
}

// ---------------------------------------------------------------------------
// Kernel 0: expand relative position bias table -> g_bias[h][n][m]
// ---------------------------------------------------------------------------
__global__ __launch_bounds__(256) void bias_expand_kernel(
    const float* __restrict__ table, const int* __restrict__ rel)
{
    int i = blockIdx.x * 256 + threadIdx.x;
    const int total = NH * NTOK2;
    if (i >= total) return;
    int h  = i / NTOK2;
    int nm = i - h * NTOK2;
    g_bias[i] = table[rel[nm] * NH + h];
}

// ---------------------------------------------------------------------------
// Kernel 1/3: TF32 GEMM  Out[m,n] = sum_k A[m,k] * W[n,k] + bias[n]
// BM=128, BN=64, BK=16, 256 threads. tf32 stored in smem with k-permutation
// [0,4,1,5,2,6,3,7] per 8-group so fragment loads are LDS.64.
// ---------------------------------------------------------------------------
#define GST 24   // smem row stride (words), 24 mod 32 = 24 -> conflict-free frags

template <int MODE>
__global__ __launch_bounds__(256) void gemm_tf32_kernel(
    const float* __restrict__ A, const float* __restrict__ W,
    const float* __restrict__ bias, float* __restrict__ Out, int Ncols)
{
    __shared__ uint32_t As[128 * GST];
    __shared__ uint32_t Bs[64 * GST];

    const int nTiles = Ncols >> 6;
    const int m_tile = blockIdx.x / nTiles;
    const int n_tile = blockIdx.x - m_tile * nTiles;
    const int m0 = m_tile * 128, n0 = n_tile * 64;

    const int tid  = threadIdx.x;
    const int warp = tid >> 5, lane = tid & 31;
    const int wm = warp >> 1;     // 0..3
    const int wn = warp & 1;      // 0..1
    const int gm = lane >> 2, gk = lane & 3;

    const float* Aptr = (MODE == 0 ? A : g_ctx) + (size_t)m0 * DIMC;
    const float* Wptr = W + (size_t)n0 * DIMC;

    // staging indices: row = tid>>2 (A also +64), k-offset acv in {0,4,8,12}
    const int ar0 = tid >> 2;
    const int acv = (tid & 3) << 2;
    // permuted store base: group base (acv & ~7), +1 if second half of 8-group
    const int sbase = (acv & ~7) + ((acv >> 2) & 1);

    float acc[2][4][4];
    #pragma unroll
    for (int i = 0; i < 2; i++)
        #pragma unroll
        for (int j = 0; j < 4; j++)
            #pragma unroll
            for (int l = 0; l < 4; l++) acc[i][j][l] = 0.f;

    // prime global prefetch
    float4 pa0 = *(const float4*)(Aptr + (size_t)ar0 * DIMC + acv);
    float4 pa1 = *(const float4*)(Aptr + (size_t)(ar0 + 64) * DIMC + acv);
    float4 pb  = *(const float4*)(Wptr + (size_t)ar0 * DIMC + acv);

    for (int k0 = 0; k0 < DIMC; k0 += 16) {
        // store staged tile (tf32, permuted)
        {
            uint32_t* d0 = &As[ar0 * GST + sbase];
            d0[0] = f2tf(pa0.x); d0[2] = f2tf(pa0.y); d0[4] = f2tf(pa0.z); d0[6] = f2tf(pa0.w);
            uint32_t* d1 = &As[(ar0 + 64) * GST + sbase];
            d1[0] = f2tf(pa1.x); d1[2] = f2tf(pa1.y); d1[4] = f2tf(pa1.z); d1[6] = f2tf(pa1.w);
            uint32_t* db = &Bs[ar0 * GST + sbase];
            db[0] = f2tf(pb.x);  db[2] = f2tf(pb.y);  db[4] = f2tf(pb.z);  db[6] = f2tf(pb.w);
        }
        __syncthreads();

        if (k0 + 16 < DIMC) {
            pa0 = *(const float4*)(Aptr + (size_t)ar0 * DIMC + k0 + 16 + acv);
            pa1 = *(const float4*)(Aptr + (size_t)(ar0 + 64) * DIMC + k0 + 16 + acv);
            pb  = *(const float4*)(Wptr + (size_t)ar0 * DIMC + k0 + 16 + acv);
        }

        #pragma unroll
        for (int kk = 0; kk < 16; kk += 8) {
            uint32_t afr[2][4], bfr[4][2];
            #pragma unroll
            for (int im = 0; im < 2; im++) {
                int rb = wm * 32 + im * 16;
                uint2 t0 = *(const uint2*)&As[(rb + gm)     * GST + kk + 2 * gk];
                uint2 t1 = *(const uint2*)&As[(rb + gm + 8) * GST + kk + 2 * gk];
                afr[im][0] = t0.x; afr[im][1] = t1.x; afr[im][2] = t0.y; afr[im][3] = t1.y;
            }
            #pragma unroll
            for (int in = 0; in < 4; in++) {
                uint2 t = *(const uint2*)&Bs[(wn * 32 + in * 8 + gm) * GST + kk + 2 * gk];
                bfr[in][0] = t.x; bfr[in][1] = t.y;
            }
            #pragma unroll
            for (int im = 0; im < 2; im++)
                #pragma unroll
                for (int in = 0; in < 4; in++)
                    mma_tf32(acc[im][in], afr[im], bfr[in]);
        }
        __syncthreads();
    }

    // epilogue: bias add + store/scatter
    #pragma unroll
    for (int im = 0; im < 2; im++) {
        #pragma unroll
        for (int half = 0; half < 2; half++) {
            int rg = m0 + wm * 32 + im * 16 + gm + half * 8;
            int b_idx = rg / NTOK;
            int ntk   = rg - b_idx * NTOK;
            #pragma unroll
            for (int in = 0; in < 4; in++) {
                int cg = n0 + wn * 32 + in * 8 + gk * 2;
                float v0 = acc[im][in][half * 2 + 0] + bias[cg];
                float v1 = acc[im][in][half * 2 + 1] + bias[cg + 1];
                if (MODE == 0) {
                    int which = cg >> 9;
                    int rem   = cg & 511;
                    int h     = rem >> 5;
                    int d     = rem & 31;
                    size_t dst = ((size_t)(which * B_TOT + b_idx) * NH + h) * BHSTRIDE
                               + (size_t)ntk * HD + d;
                    *(float2*)&g_qkv[dst] = make_float2(v0, v1);
                } else {
                    *(float2*)&Out[(size_t)rg * DIMC + cg] = make_float2(v0, v1);
                }
            }
        }
    }
}

// ---------------------------------------------------------------------------
// Kernel 2: attention per (b,h). 288 threads (9 warps), warp-per-16-row tile.
// ---------------------------------------------------------------------------
#define QST 36    // q/k/v smem stride (36 mod 32 = 4 -> conflict-free frag LDS)
#define SST 164   // scores stride (164 mod 32 = 4)
#define ATTN_SMEM ((3 * NTOK * QST + NTOK * SST) * 4)   // 156672 B

__global__ __launch_bounds__(288) void attn_kernel(const float* __restrict__ mask)
{
    extern __shared__ uint32_t sm[];
    uint32_t* sq  = sm;
    uint32_t* sk  = sq + NTOK * QST;
    uint32_t* sv  = sk + NTOK * QST;
    float*    sS  = (float*)(sv + NTOK * QST);
    uint32_t* sSu = (uint32_t*)sS;

    const int bh = blockIdx.x;
    const int b  = bh >> 4, h = bh & 15;
    const int w  = b % NWIN;

    const int tid  = threadIdx.x;
    const int warp = tid >> 5, lane = tid & 31;
    const int gm = lane >> 2, gk = lane & 3;

    const float* __restrict__ qg = g_qkv + ((size_t)(0 * B_TOT + b) * NH + h) * BHSTRIDE;
    const float* __restrict__ kg = g_qkv + ((size_t)(1 * B_TOT + b) * NH + h) * BHSTRIDE;
    const float* __restrict__ vg = g_qkv + ((size_t)(2 * B_TOT + b) * NH + h) * BHSTRIDE;

    // stage q,k,v as tf32 (plain layout)
    for (int i = tid; i < NTOK * HD / 4; i += 288) {
        int r = i >> 3, d0 = (i & 7) << 2;
        float4 t;
        t = *(const float4*)(qg + (size_t)r * HD + d0);
        { uint4 u = {f2tf(t.x), f2tf(t.y), f2tf(t.z), f2tf(t.w)};
          *(uint4*)&sq[r * QST + d0] = u; }
        t = *(const float4*)(kg + (size_t)r * HD + d0);
        { uint4 u = {f2tf(t.x), f2tf(t.y), f2tf(t.z), f2tf(t.w)};
          *(uint4*)&sk[r * QST + d0] = u; }
        t = *(const float4*)(vg + (size_t)r * HD + d0);
        { uint4 u = {f2tf(t.x), f2tf(t.y), f2tf(t.z), f2tf(t.w)};
          *(uint4*)&sv[r * QST + d0] = u; }
    }
    __syncthreads();

    const float* __restrict__ biasp = g_bias + (size_t)h * NTOK2;
    const float* __restrict__ maskp = mask   + (size_t)w * NTOK2;

    const int rb = warp * 16;      // warp 0..8 -> row tile

    // ---- S = scale*q@k^T + bias + mask ----
    // Q fragments loaded once, reused across 18 column tiles
    uint32_t afr[4][4];
    #pragma unroll
    for (int k8 = 0; k8 < 4; k8++) {
        const uint32_t* p0 = &sq[(rb + gm)     * QST + k8 * 8 + gk];
        const uint32_t* p1 = &sq[(rb + gm + 8) * QST + k8 * 8 + gk];
        afr[k8][0] = p0[0]; afr[k8][1] = p1[0]; afr[k8][2] = p0[4]; afr[k8][3] = p1[4];
    }

    float2 bv0, bv1, mv0, mv1;
    {
        int c = gk * 2;
        bv0 = *(const float2*)&biasp[(rb + gm)     * NTOK + c];
        bv1 = *(const float2*)&biasp[(rb + gm + 8) * NTOK + c];
        mv0 = *(const float2*)&maskp[(rb + gm)     * NTOK + c];
        mv1 = *(const float2*)&maskp[(rb + gm + 8) * NTOK + c];
    }

    for (int ni = 0; ni < 18; ni++) {
        float2 cb0 = bv0, cb1 = bv1, cm0 = mv0, cm1 = mv1;
        if (ni < 17) {   // prefetch next tile's bias+mask
            int c = (ni + 1) * 8 + gk * 2;
            bv0 = *(const float2*)&biasp[(rb + gm)     * NTOK + c];
            bv1 = *(const float2*)&biasp[(rb + gm + 8) * NTOK + c];
            mv0 = *(const float2*)&maskp[(rb + gm)     * NTOK + c];
            mv1 = *(const float2*)&maskp[(rb + gm + 8) * NTOK + c];
        }
        float acc[4] = {0.f, 0.f, 0.f, 0.f};
        #pragma unroll
        for (int k8 = 0; k8 < 4; k8++) {
            const uint32_t* pb = &sk[(ni * 8 + gm) * QST + k8 * 8 + gk];
            uint32_t bfr[2] = {pb[0], pb[4]};
            mma_tf32(acc, afr[k8], bfr);
        }
        int c = ni * 8 + gk * 2;
        float2 o0, o1;
        o0.x = acc[0] * SCALE + cb0.x + cm0.x;
        o0.y = acc[1] * SCALE + cb0.y + cm0.y;
        o1.x = acc[2] * SCALE + cb1.x + cm1.x;
        o1.y = acc[3] * SCALE + cb1.y + cm1.y;
        *(float2*)&sS[(rb + gm)     * SST + c] = o0;
        *(float2*)&sS[(rb + gm + 8) * SST + c] = o1;
    }
    __syncthreads();

    // ---- warp-parallel softmax over the warp's 16 rows ----
    for (int rr = 0; rr < 16; rr++) {
        float* row = &sS[(rb + rr) * SST];
        float mx = -1e30f;
        for (int j = lane; j < NTOK; j += 32) mx = fmaxf(mx, row[j]);
        #pragma unroll
        for (int o = 16; o; o >>= 1) mx = fmaxf(mx, __shfl_xor_sync(0xffffffffu, mx, o));
        float s = 0.f;
        for (int j = lane; j < NTOK; j += 32) {
            float e = __expf(row[j] - mx);
            row[j] = e;
            s += e;
        }
        #pragma unroll
        for (int o = 16; o; o >>= 1) s += __shfl_xor_sync(0xffffffffu, s, o);
        float inv = 1.f / s;
        for (int j = lane; j < NTOK; j += 32)
            ((uint32_t*)row)[j] = f2tf(row[j] * inv);
    }
    __syncthreads();

    // ---- O = P @ v  -> g_ctx[b, n, h*32 + d] ----
    float acc[4][4];
    #pragma unroll
    for (int nd = 0; nd < 4; nd++)
        #pragma unroll
        for (int l = 0; l < 4; l++) acc[nd][l] = 0.f;

    for (int k8 = 0; k8 < 18; k8++) {
        const uint32_t* pa0 = &sSu[(rb + gm)     * SST + k8 * 8 + gk];
        const uint32_t* pa1 = &sSu[(rb + gm + 8) * SST + k8 * 8 + gk];
        uint32_t af[4] = {pa0[0], pa1[0], pa0[4], pa1[4]};
        #pragma unroll
        for (int nd = 0; nd < 4; nd++) {
            uint32_t bf[2] = {sv[(k8 * 8 + gk)     * QST + nd * 8 + gm],
                              sv[(k8 * 8 + gk + 4) * QST + nd * 8 + gm]};
            mma_tf32(acc[nd], af, bf);
        }
    }

    const size_t ob = (size_t)b * NTOK * DIMC + (size_t)h * HD;
    #pragma unroll
    for (int nd = 0; nd < 4; nd++) {
        int c = nd * 8 + gk * 2;
        *(float2*)&g_ctx[ob + (size_t)(rb + gm)     * DIMC + c] =
            make_float2(acc[nd][0], acc[nd][1]);
        *(float2*)&g_ctx[ob + (size_t)(rb + gm + 8) * DIMC + c] =
            make_float2(acc[nd][2], acc[nd][3]);
    }
}

// ---------------------------------------------------------------------------
// launch
// ---------------------------------------------------------------------------
extern "C" void kernel_launch(void* const* d_in, const int* in_sizes, int n_in,
                              void* d_out, int out_size)
{
    const float* x      = (const float*)d_in[0];
    const float* mask   = (const float*)d_in[1];
    const float* qkv_w  = (const float*)d_in[2];
    const float* qkv_b  = (const float*)d_in[3];
    const float* proj_w = (const float*)d_in[4];
    const float* proj_b = (const float*)d_in[5];
    const float* table  = (const float*)d_in[6];
    const int*   rel    = (const int*)d_in[7];
    float* out = (float*)d_out;

    // 0: bias expand
    bias_expand_kernel<<<(NH * NTOK2 + 255) / 256, 256>>>(table, rel);

    // 1: QKV GEMM (M=110592, N=1536) -> g_qkv
    gemm_tf32_kernel<0><<<864 * 24, 256>>>(x, qkv_w, qkv_b, nullptr, 1536);

    // 2: attention
    cudaFuncSetAttribute(attn_kernel, cudaFuncAttributeMaxDynamicSharedMemorySize, ATTN_SMEM);
    attn_kernel<<<B_TOT * NH, 288, ATTN_SMEM>>>(mask);

    // 3: proj GEMM (M=110592, N=512) -> out
    gemm_tf32_kernel<1><<<864 * 8, 256>>>(nullptr, proj_w, proj_b, out, 512);
}

// round 5
// speedup vs baseline: 1.0216x; 1.0216x over previous
#include <cuda_runtime.h>
#include <cstdint>

// ---------------------------------------------------------------------------
// WindowAttention3D: B=768, N=144, C=512, H=16, hd=32, NW=96
// Round 5: R1 structure; tf32 converted once at SMEM staging (no inner-loop
//          CVT anywhere); warp-parallel softmax. mma.sync tf32 path.
// ---------------------------------------------------------------------------

#define B_TOT   768
#define NTOK    144
#define DIMC    512
#define NH      16
#define HD      32
#define NWIN    96
#define SCALE   0.17677669529663687f   // 1/sqrt(32)
#define NTOK2   (NTOK*NTOK)            // 20736
#define BHSTRIDE (NTOK*HD)             // 4608

// Scratch (device globals; allocation-free rule)
__device__ float g_qkv[3u*768u*16u*144u*32u];   // [3][B][H][N][hd]
__device__ float g_ctx[768u*144u*512u];         // [B][N][C]
__device__ float g_bias[16u*144u*144u];         // [H][N][N]

// ---------------------------------------------------------------------------
__device__ __forceinline__ uint32_t f2tf(float x) {
    uint32_t r;
    asm("cvt.rna.tf32.f32 %0, %1;" : "=r"(r) : "f"(x));
    return r;
}

__device__ __forceinline__ uint4 f2tf4(float4 v) {
    uint4 u;
    u.x = f2tf(v.x); u.y = f2tf(v.y); u.z = f2tf(v.z); u.w = f2tf(v.w);
    return u;
}

__device__ __forceinline__ void mma_tf32(float* c, const uint32_t* a, const uint32_t* b) {
    asm volatile(
        "mma.sync.aligned.m16n8k8.row.col.f32.tf32.tf32.f32 "
        "{%0,%1,%2,%3},{%4,%5,%6,%7},{%8,%9},{%0,%1,%2,%3};\n"
        : "+f"(c[0]), "+f"(c[1]), "+f"(c[2]), "+f"(c[3])
        : "r"(a[0]), "r"(a[1]), "r"(a[2]), "r"(a[3]), "r"(b[0]), "r"(b[1]));
}

// ---------------------------------------------------------------------------
// Kernel 0: expand relative position bias table -> g_bias[h][n][m]
// ---------------------------------------------------------------------------
__global__ __launch_bounds__(256) void bias_expand_kernel(
    const float* __restrict__ table, const int* __restrict__ rel)
{
    int i = blockIdx.x * 256 + threadIdx.x;
    const int total = NH * NTOK2;
    if (i >= total) return;
    int h  = i / NTOK2;
    int nm = i - h * NTOK2;
    g_bias[i] = table[rel[nm] * NH + h];
}

// ---------------------------------------------------------------------------
// Kernel 1/3: TF32 GEMM  Out[m,n] = sum_k A[m,k] * W[n,k] + bias[n]
// BM=128, BN=64, BK=16, 256 threads. tf32 stored at staging (STS.128),
// fragment loads are raw LDS.32 (no CVT in inner loop). R1 layout exactly.
// ---------------------------------------------------------------------------
template <int MODE>
__global__ __launch_bounds__(256) void gemm_tf32_kernel(
    const float* __restrict__ A, const float* __restrict__ W,
    const float* __restrict__ bias, float* __restrict__ Out, int Ncols)
{
    __shared__ uint32_t As[128][20];
    __shared__ uint32_t Bs[64][20];

    const int nTiles = Ncols >> 6;
    const int m_tile = blockIdx.x / nTiles;
    const int n_tile = blockIdx.x - m_tile * nTiles;
    const int m0 = m_tile * 128, n0 = n_tile * 64;

    const int tid  = threadIdx.x;
    const int warp = tid >> 5, lane = tid & 31;
    const int wm = warp >> 1;     // 0..3  (32 rows each)
    const int wn = warp & 1;      // 0..1  (32 cols each)
    const int gm = lane >> 2, gk = lane & 3;

    const float* Aptr = (MODE == 0 ? A : g_ctx) + (size_t)m0 * DIMC;
    const float* Wptr = W + (size_t)n0 * DIMC;

    float acc[2][4][4];
    #pragma unroll
    for (int i = 0; i < 2; i++)
        #pragma unroll
        for (int j = 0; j < 4; j++)
            #pragma unroll
            for (int l = 0; l < 4; l++) acc[i][j][l] = 0.f;

    for (int k0 = 0; k0 < DIMC; k0 += 16) {
        __syncthreads();
        // load A tile 128x16 (convert to tf32 at store)
        #pragma unroll
        for (int r = 0; r < 2; r++) {
            int lin = r * 256 + tid;
            int row = lin >> 2, cv = (lin & 3) << 2;
            float4 t = *(const float4*)(Aptr + (size_t)row * DIMC + k0 + cv);
            *(uint4*)&As[row][cv] = f2tf4(t);
        }
        // load B tile 64x16
        {
            int row = tid >> 2, cv = (tid & 3) << 2;
            float4 t = *(const float4*)(Wptr + (size_t)row * DIMC + k0 + cv);
            *(uint4*)&Bs[row][cv] = f2tf4(t);
        }
        __syncthreads();

        #pragma unroll
        for (int kk = 0; kk < 16; kk += 8) {
            uint32_t afr[2][4], bfr[4][2];
            #pragma unroll
            for (int im = 0; im < 2; im++) {
                int rb = wm * 32 + im * 16;
                afr[im][0] = As[rb + gm    ][kk + gk    ];
                afr[im][1] = As[rb + gm + 8][kk + gk    ];
                afr[im][2] = As[rb + gm    ][kk + gk + 4];
                afr[im][3] = As[rb + gm + 8][kk + gk + 4];
            }
            #pragma unroll
            for (int in = 0; in < 4; in++) {
                int cb = wn * 32 + in * 8;
                bfr[in][0] = Bs[cb + gm][kk + gk    ];
                bfr[in][1] = Bs[cb + gm][kk + gk + 4];
            }
            #pragma unroll
            for (int im = 0; im < 2; im++)
                #pragma unroll
                for (int in = 0; in < 4; in++)
                    mma_tf32(acc[im][in], afr[im], bfr[in]);
        }
    }

    // store
    #pragma unroll
    for (int im = 0; im < 2; im++) {
        #pragma unroll
        for (int half = 0; half < 2; half++) {
            int rg = m0 + wm * 32 + im * 16 + gm + half * 8;
            int b_idx = rg / NTOK;
            int ntk   = rg - b_idx * NTOK;
            #pragma unroll
            for (int in = 0; in < 4; in++) {
                int cg = n0 + wn * 32 + in * 8 + gk * 2;
                float v0 = acc[im][in][half * 2 + 0] + bias[cg];
                float v1 = acc[im][in][half * 2 + 1] + bias[cg + 1];
                if (MODE == 0) {
                    int which = cg >> 9;
                    int rem   = cg & 511;
                    int h     = rem >> 5;
                    int d     = rem & 31;
                    size_t dst = ((size_t)(which * B_TOT + b_idx) * NH + h) * BHSTRIDE
                               + (size_t)ntk * HD + d;
                    *(float2*)&g_qkv[dst] = make_float2(v0, v1);
                } else {
                    *(float2*)&Out[(size_t)rg * DIMC + cg] = make_float2(v0, v1);
                }
            }
        }
    }
}

// ---------------------------------------------------------------------------
// Kernel 2: attention per (b,h). 256 threads, 143KB dyn smem. R1 structure;
// q/k/v staged as tf32; P stored as tf32 by softmax; no inner-loop CVT.
// ---------------------------------------------------------------------------
#define SQ_STRIDE 36
#define SS_STRIDE 146
#define ATTN_SMEM ((3 * NTOK * SQ_STRIDE + NTOK * SS_STRIDE) * 4)

__global__ __launch_bounds__(256) void attn_kernel(const float* __restrict__ mask)
{
    extern __shared__ uint32_t sm[];
    uint32_t* sq = sm;
    uint32_t* sk = sq + NTOK * SQ_STRIDE;
    uint32_t* sv = sk + NTOK * SQ_STRIDE;
    float*    sS = (float*)(sv + NTOK * SQ_STRIDE);
    uint32_t* sSu = (uint32_t*)sS;

    const int bh = blockIdx.x;
    const int b  = bh >> 4, h = bh & 15;
    const int w  = b % NWIN;

    const int tid  = threadIdx.x;
    const int warp = tid >> 5, lane = tid & 31;
    const int gm = lane >> 2, gk = lane & 3;

    const size_t qbase = ((size_t)(0 * B_TOT + b) * NH + h) * BHSTRIDE;
    const size_t kbase = ((size_t)(1 * B_TOT + b) * NH + h) * BHSTRIDE;
    const size_t vbase = ((size_t)(2 * B_TOT + b) * NH + h) * BHSTRIDE;

    // load q,k,v tiles [144][32] into padded smem, converting to tf32
    for (int i = tid; i < (NTOK * HD / 4); i += 256) {
        int row = i >> 3;
        int d   = (i & 7) << 2;
        *(uint4*)&sq[row * SQ_STRIDE + d] = f2tf4(*(const float4*)&g_qkv[qbase + (size_t)row * HD + d]);
        *(uint4*)&sk[row * SQ_STRIDE + d] = f2tf4(*(const float4*)&g_qkv[kbase + (size_t)row * HD + d]);
        *(uint4*)&sv[row * SQ_STRIDE + d] = f2tf4(*(const float4*)&g_qkv[vbase + (size_t)row * HD + d]);
    }
    __syncthreads();

    const float* biasp = g_bias + (size_t)h * NTOK2;
    const float* maskp = mask   + (size_t)w * NTOK2;

    // ---- S = scale * q @ k^T + bias + mask ----
    for (int t = warp; t < 9 * 18; t += 8) {
        int mi = t / 18, ni = t - mi * 18;
        float acc[4] = {0.f, 0.f, 0.f, 0.f};
        #pragma unroll
        for (int k8 = 0; k8 < 4; k8++) {
            int d0 = k8 * 8;
            uint32_t a[4], bb[2];
            int rb = mi * 16;
            a[0] = sq[(rb + gm    ) * SQ_STRIDE + d0 + gk    ];
            a[1] = sq[(rb + gm + 8) * SQ_STRIDE + d0 + gk    ];
            a[2] = sq[(rb + gm    ) * SQ_STRIDE + d0 + gk + 4];
            a[3] = sq[(rb + gm + 8) * SQ_STRIDE + d0 + gk + 4];
            bb[0] = sk[(ni * 8 + gm) * SQ_STRIDE + d0 + gk    ];
            bb[1] = sk[(ni * 8 + gm) * SQ_STRIDE + d0 + gk + 4];
            mma_tf32(acc, a, bb);
        }
        #pragma unroll
        for (int half = 0; half < 2; half++) {
            int r = mi * 16 + gm + half * 8;
            int c = ni * 8 + gk * 2;
            float2 bv = *(const float2*)&biasp[r * NTOK + c];
            float2 mv = *(const float2*)&maskp[r * NTOK + c];
            float2 o;
            o.x = acc[half * 2 + 0] * SCALE + bv.x + mv.x;
            o.y = acc[half * 2 + 1] * SCALE + bv.y + mv.y;
            *(float2*)&sS[r * SS_STRIDE + c] = o;
        }
    }
    __syncthreads();

    // ---- warp-parallel softmax: warp handles rows [warp*18, warp*18+18) ----
    for (int rr = 0; rr < 18; rr++) {
        float* row = &sS[(warp * 18 + rr) * SS_STRIDE];
        float mx = -1e30f;
        for (int j = lane; j < NTOK; j += 32) mx = fmaxf(mx, row[j]);
        #pragma unroll
        for (int o = 16; o; o >>= 1) mx = fmaxf(mx, __shfl_xor_sync(0xffffffffu, mx, o));
        float s = 0.f;
        for (int j = lane; j < NTOK; j += 32) {
            float e = __expf(row[j] - mx);
            row[j] = e;
            s += e;
        }
        #pragma unroll
        for (int o = 16; o; o >>= 1) s += __shfl_xor_sync(0xffffffffu, s, o);
        float inv = 1.f / s;
        for (int j = lane; j < NTOK; j += 32)
            ((uint32_t*)row)[j] = f2tf(row[j] * inv);   // P stored as tf32 bits
    }
    __syncthreads();

    // ---- O = P @ v  -> g_ctx[b, n, h*32 + d] ----
    const size_t obase = (size_t)b * NTOK * DIMC + (size_t)h * HD;
    for (int t = warp; t < 9 * 4; t += 8) {
        int mi = t >> 2, nd = t & 3;
        float acc[4] = {0.f, 0.f, 0.f, 0.f};
        #pragma unroll
        for (int k8 = 0; k8 < 18; k8++) {
            int k0 = k8 * 8;
            uint32_t a[4], bb[2];
            int rb = mi * 16;
            a[0] = sSu[(rb + gm    ) * SS_STRIDE + k0 + gk    ];
            a[1] = sSu[(rb + gm + 8) * SS_STRIDE + k0 + gk    ];
            a[2] = sSu[(rb + gm    ) * SS_STRIDE + k0 + gk + 4];
            a[3] = sSu[(rb + gm + 8) * SS_STRIDE + k0 + gk + 4];
            bb[0] = sv[(k0 + gk    ) * SQ_STRIDE + nd * 8 + gm];
            bb[1] = sv[(k0 + gk + 4) * SQ_STRIDE + nd * 8 + gm];
            mma_tf32(acc, a, bb);
        }
        #pragma unroll
        for (int half = 0; half < 2; half++) {
            int r = mi * 16 + gm + half * 8;
            int dc = nd * 8 + gk * 2;
            *(float2*)&g_ctx[obase + (size_t)r * DIMC + dc] =
                make_float2(acc[half * 2 + 0], acc[half * 2 + 1]);
        }
    }
}

// ---------------------------------------------------------------------------
// launch
// ---------------------------------------------------------------------------
extern "C" void kernel_launch(void* const* d_in, const int* in_sizes, int n_in,
                              void* d_out, int out_size)
{
    const float* x      = (const float*)d_in[0];
    const float* mask   = (const float*)d_in[1];
    const float* qkv_w  = (const float*)d_in[2];
    const float* qkv_b  = (const float*)d_in[3];
    const float* proj_w = (const float*)d_in[4];
    const float* proj_b = (const float*)d_in[5];
    const float* table  = (const float*)d_in[6];
    const int*   rel    = (const int*)d_in[7];
    float* out = (float*)d_out;

    // 0: bias expand
    bias_expand_kernel<<<(NH * NTOK2 + 255) / 256, 256>>>(table, rel);

    // 1: QKV GEMM (M=110592, N=1536) -> g_qkv
    gemm_tf32_kernel<0><<<864 * 24, 256>>>(x, qkv_w, qkv_b, nullptr, 1536);

    // 2: attention
    cudaFuncSetAttribute(attn_kernel, cudaFuncAttributeMaxDynamicSharedMemorySize, ATTN_SMEM);
    attn_kernel<<<B_TOT * NH, 256, ATTN_SMEM>>>(mask);

    // 3: proj GEMM (M=110592, N=512) -> out
    gemm_tf32_kernel<1><<<864 * 8, 256>>>(nullptr, proj_w, proj_b, out, 512);
}

// round 8
// speedup vs baseline: 1.5804x; 1.5470x over previous
#include <cuda_runtime.h>
#include <cstdint>

// ---------------------------------------------------------------------------
// WindowAttention3D: B=768, N=144, C=512, H=16, hd=32, NW=96
// Round 6: flash-style register-resident attention (scores never in SMEM,
//          quad-shfl softmax, shfl repack C->A frag for PV). GEMMs = R5.
// ---------------------------------------------------------------------------

#define B_TOT   768
#define NTOK    144
#define DIMC    512
#define NH      16
#define HD      32
#define NWIN    96
#define SCALE   0.17677669529663687f   // 1/sqrt(32)
#define NTOK2   (NTOK*NTOK)            // 20736
#define BHSTRIDE (NTOK*HD)             // 4608

// Scratch (device globals; allocation-free rule)
__device__ float g_qkv[3u*768u*16u*144u*32u];   // [3][B][H][N][hd]
__device__ float g_ctx[768u*144u*512u];         // [B][N][C]
__device__ float g_bias[16u*144u*144u];         // [H][N][N]

// ---------------------------------------------------------------------------
__device__ __forceinline__ uint32_t f2tf(float x) {
    uint32_t r;
    asm("cvt.rna.tf32.f32 %0, %1;" : "=r"(r) : "f"(x));
    return r;
}

__device__ __forceinline__ uint4 f2tf4(float4 v) {
    uint4 u;
    u.x = f2tf(v.x); u.y = f2tf(v.y); u.z = f2tf(v.z); u.w = f2tf(v.w);
    return u;
}

__device__ __forceinline__ void mma_tf32(float* c, const uint32_t* a, const uint32_t* b) {
    asm volatile(
        "mma.sync.aligned.m16n8k8.row.col.f32.tf32.tf32.f32 "
        "{%0,%1,%2,%3},{%4,%5,%6,%7},{%8,%9},{%0,%1,%2,%3};\n"
        : "+f"(c[0]), "+f"(c[1]), "+f"(c[2]), "+f"(c[3])
        : "r"(a[0]), "r"(a[1]), "r"(a[2]), "r"(a[3]), "r"(b[0]), "r"(b[1]));
}

// ---------------------------------------------------------------------------
// Kernel 0: expand relative position bias table -> g_bias[h][n][m]
// ---------------------------------------------------------------------------
__global__ __launch_bounds__(256) void bias_expand_kernel(
    const float* __restrict__ table, const int* __restrict__ rel)
{
    int i = blockIdx.x * 256 + threadIdx.x;
    const int total = NH * NTOK2;
    if (i >= total) return;
    int h  = i / NTOK2;
    int nm = i - h * NTOK2;
    g_bias[i] = table[rel[nm] * NH + h];
}

// ---------------------------------------------------------------------------
// Kernel 1/3: TF32 GEMM (unchanged from R5: tf32 staged, raw LDS frags)
// ---------------------------------------------------------------------------
template <int MODE>
__global__ __launch_bounds__(256) void gemm_tf32_kernel(
    const float* __restrict__ A, const float* __restrict__ W,
    const float* __restrict__ bias, float* __restrict__ Out, int Ncols)
{
    __shared__ uint32_t As[128][20];
    __shared__ uint32_t Bs[64][20];

    const int nTiles = Ncols >> 6;
    const int m_tile = blockIdx.x / nTiles;
    const int n_tile = blockIdx.x - m_tile * nTiles;
    const int m0 = m_tile * 128, n0 = n_tile * 64;

    const int tid  = threadIdx.x;
    const int warp = tid >> 5, lane = tid & 31;
    const int wm = warp >> 1;
    const int wn = warp & 1;
    const int gm = lane >> 2, gk = lane & 3;

    const float* Aptr = (MODE == 0 ? A : g_ctx) + (size_t)m0 * DIMC;
    const float* Wptr = W + (size_t)n0 * DIMC;

    float acc[2][4][4];
    #pragma unroll
    for (int i = 0; i < 2; i++)
        #pragma unroll
        for (int j = 0; j < 4; j++)
            #pragma unroll
            for (int l = 0; l < 4; l++) acc[i][j][l] = 0.f;

    for (int k0 = 0; k0 < DIMC; k0 += 16) {
        __syncthreads();
        #pragma unroll
        for (int r = 0; r < 2; r++) {
            int lin = r * 256 + tid;
            int row = lin >> 2, cv = (lin & 3) << 2;
            float4 t = *(const float4*)(Aptr + (size_t)row * DIMC + k0 + cv);
            *(uint4*)&As[row][cv] = f2tf4(t);
        }
        {
            int row = tid >> 2, cv = (tid & 3) << 2;
            float4 t = *(const float4*)(Wptr + (size_t)row * DIMC + k0 + cv);
            *(uint4*)&Bs[row][cv] = f2tf4(t);
        }
        __syncthreads();

        #pragma unroll
        for (int kk = 0; kk < 16; kk += 8) {
            uint32_t afr[2][4], bfr[4][2];
            #pragma unroll
            for (int im = 0; im < 2; im++) {
                int rb = wm * 32 + im * 16;
                afr[im][0] = As[rb + gm    ][kk + gk    ];
                afr[im][1] = As[rb + gm + 8][kk + gk    ];
                afr[im][2] = As[rb + gm    ][kk + gk + 4];
                afr[im][3] = As[rb + gm + 8][kk + gk + 4];
            }
            #pragma unroll
            for (int in = 0; in < 4; in++) {
                int cb = wn * 32 + in * 8;
                bfr[in][0] = Bs[cb + gm][kk + gk    ];
                bfr[in][1] = Bs[cb + gm][kk + gk + 4];
            }
            #pragma unroll
            for (int im = 0; im < 2; im++)
                #pragma unroll
                for (int in = 0; in < 4; in++)
                    mma_tf32(acc[im][in], afr[im], bfr[in]);
        }
    }

    #pragma unroll
    for (int im = 0; im < 2; im++) {
        #pragma unroll
        for (int half = 0; half < 2; half++) {
            int rg = m0 + wm * 32 + im * 16 + gm + half * 8;
            int b_idx = rg / NTOK;
            int ntk   = rg - b_idx * NTOK;
            #pragma unroll
            for (int in = 0; in < 4; in++) {
                int cg = n0 + wn * 32 + in * 8 + gk * 2;
                float v0 = acc[im][in][half * 2 + 0] + bias[cg];
                float v1 = acc[im][in][half * 2 + 1] + bias[cg + 1];
                if (MODE == 0) {
                    int which = cg >> 9;
                    int rem   = cg & 511;
                    int h     = rem >> 5;
                    int d     = rem & 31;
                    size_t dst = ((size_t)(which * B_TOT + b_idx) * NH + h) * BHSTRIDE
                               + (size_t)ntk * HD + d;
                    *(float2*)&g_qkv[dst] = make_float2(v0, v1);
                } else {
                    *(float2*)&Out[(size_t)rg * DIMC + cg] = make_float2(v0, v1);
                }
            }
        }
    }
}

// ---------------------------------------------------------------------------
// Kernel 2: flash-style attention per (b,h). 288 threads (9 warps), each warp
// owns 16 rows; scores live in registers (p[18][4]); quad-shfl softmax;
// shfl repack C-frag -> A-frag for PV. SMEM: q,k,v only (61KB).
// ---------------------------------------------------------------------------
#define AQ_ST 36
#define ATTN_SMEM (3 * NTOK * AQ_ST * 4)   // 62208 B

__global__ __launch_bounds__(288, 1) void attn_kernel(const float* __restrict__ mask)
{
    extern __shared__ uint32_t sm[];
    uint32_t* sq = sm;
    uint32_t* sk = sq + NTOK * AQ_ST;
    uint32_t* sv = sk + NTOK * AQ_ST;

    const int bh = blockIdx.x;
    const int b  = bh >> 4, h = bh & 15;
    const int w  = b % NWIN;

    const int tid  = threadIdx.x;
    const int warp = tid >> 5, lane = tid & 31;
    const int gm = lane >> 2, gk = lane & 3;
    const int rb = warp * 16;

    const size_t qbase = ((size_t)(0 * B_TOT + b) * NH + h) * BHSTRIDE;
    const size_t kbase = ((size_t)(1 * B_TOT + b) * NH + h) * BHSTRIDE;
    const size_t vbase = ((size_t)(2 * B_TOT + b) * NH + h) * BHSTRIDE;

    // stage q,k,v [144][32] as tf32, padded stride 36
    for (int i = tid; i < (NTOK * HD / 4); i += 288) {
        int row = i >> 3;
        int d   = (i & 7) << 2;
        *(uint4*)&sq[row * AQ_ST + d] = f2tf4(*(const float4*)&g_qkv[qbase + (size_t)row * HD + d]);
        *(uint4*)&sk[row * AQ_ST + d] = f2tf4(*(const float4*)&g_qkv[kbase + (size_t)row * HD + d]);
        *(uint4*)&sv[row * AQ_ST + d] = f2tf4(*(const float4*)&g_qkv[vbase + (size_t)row * HD + d]);
    }
    __syncthreads();

    const float* __restrict__ biasp = g_bias + (size_t)h * NTOK2;
    const float* __restrict__ maskp = mask   + (size_t)w * NTOK2;

    // Q fragments (loaded once, reused for all 18 column tiles)
    uint32_t qf[4][4];
    #pragma unroll
    for (int k8 = 0; k8 < 4; k8++) {
        qf[k8][0] = sq[(rb + gm    ) * AQ_ST + k8 * 8 + gk    ];
        qf[k8][1] = sq[(rb + gm + 8) * AQ_ST + k8 * 8 + gk    ];
        qf[k8][2] = sq[(rb + gm    ) * AQ_ST + k8 * 8 + gk + 4];
        qf[k8][3] = sq[(rb + gm + 8) * AQ_ST + k8 * 8 + gk + 4];
    }

    // ---- S = scale*q@k^T + bias + mask, kept in registers p[18][4] ----
    // layout: p[ni][0]=(gm, ni*8+2gk), [1]=(gm, +1), [2]=(gm+8, 2gk), [3]=(gm+8, +1)
    float p[18][4];
    #pragma unroll
    for (int ni = 0; ni < 18; ni++) {
        float acc[4] = {0.f, 0.f, 0.f, 0.f};
        #pragma unroll
        for (int k8 = 0; k8 < 4; k8++) {
            uint32_t bb[2] = {sk[(ni * 8 + gm) * AQ_ST + k8 * 8 + gk],
                              sk[(ni * 8 + gm) * AQ_ST + k8 * 8 + gk + 4]};
            mma_tf32(acc, qf[k8], bb);
        }
        int c = ni * 8 + gk * 2;
        float2 b0 = *(const float2*)&biasp[(rb + gm)     * NTOK + c];
        float2 b1 = *(const float2*)&biasp[(rb + gm + 8) * NTOK + c];
        float2 m0 = *(const float2*)&maskp[(rb + gm)     * NTOK + c];
        float2 m1 = *(const float2*)&maskp[(rb + gm + 8) * NTOK + c];
        p[ni][0] = acc[0] * SCALE + b0.x + m0.x;
        p[ni][1] = acc[1] * SCALE + b0.y + m0.y;
        p[ni][2] = acc[2] * SCALE + b1.x + m1.x;
        p[ni][3] = acc[3] * SCALE + b1.y + m1.y;
    }

    // ---- softmax in registers: rows gm (p0,p1) and gm+8 (p2,p3) ----
    float mx0 = -1e30f, mx1 = -1e30f;
    #pragma unroll
    for (int ni = 0; ni < 18; ni++) {
        mx0 = fmaxf(mx0, fmaxf(p[ni][0], p[ni][1]));
        mx1 = fmaxf(mx1, fmaxf(p[ni][2], p[ni][3]));
    }
    mx0 = fmaxf(mx0, __shfl_xor_sync(0xffffffffu, mx0, 1));
    mx1 = fmaxf(mx1, __shfl_xor_sync(0xffffffffu, mx1, 1));
    mx0 = fmaxf(mx0, __shfl_xor_sync(0xffffffffu, mx0, 2));
    mx1 = fmaxf(mx1, __shfl_xor_sync(0xffffffffu, mx1, 2));

    float s0 = 0.f, s1 = 0.f;
    #pragma unroll
    for (int ni = 0; ni < 18; ni++) {
        p[ni][0] = __expf(p[ni][0] - mx0);
        p[ni][1] = __expf(p[ni][1] - mx0);
        p[ni][2] = __expf(p[ni][2] - mx1);
        p[ni][3] = __expf(p[ni][3] - mx1);
        s0 += p[ni][0] + p[ni][1];
        s1 += p[ni][2] + p[ni][3];
    }
    s0 += __shfl_xor_sync(0xffffffffu, s0, 1);
    s1 += __shfl_xor_sync(0xffffffffu, s1, 1);
    s0 += __shfl_xor_sync(0xffffffffu, s0, 2);
    s1 += __shfl_xor_sync(0xffffffffu, s1, 2);
    const float inv0 = 1.f / s0, inv1 = 1.f / s1;
    #pragma unroll
    for (int ni = 0; ni < 18; ni++) {
        p[ni][0] *= inv0; p[ni][1] *= inv0;
        p[ni][2] *= inv1; p[ni][3] *= inv1;
    }

    // ---- O = P @ v: repack P (C-frag) -> A-frag via quad shfl, mma with v ----
    float vacc[4][4];
    #pragma unroll
    for (int nd = 0; nd < 4; nd++)
        #pragma unroll
        for (int l = 0; l < 4; l++) vacc[nd][l] = 0.f;

    const int base   = lane & ~3;
    const int src01  = base + (gk >> 1);       // holder of col gk   (elem gk&1)
    const int src23  = src01 + 2;              // holder of col gk+4 (elem gk&1)
    const bool odd   = (gk & 1);

    #pragma unroll
    for (int ni = 0; ni < 18; ni++) {
        float t0 = __shfl_sync(0xffffffffu, p[ni][0], src01);
        float t1 = __shfl_sync(0xffffffffu, p[ni][1], src01);
        float t2 = __shfl_sync(0xffffffffu, p[ni][2], src01);
        float t3 = __shfl_sync(0xffffffffu, p[ni][3], src01);
        float u0 = __shfl_sync(0xffffffffu, p[ni][0], src23);
        float u1 = __shfl_sync(0xffffffffu, p[ni][1], src23);
        float u2 = __shfl_sync(0xffffffffu, p[ni][2], src23);
        float u3 = __shfl_sync(0xffffffffu, p[ni][3], src23);
        uint32_t af[4];
        af[0] = f2tf(odd ? t1 : t0);   // (gm,   k=ni*8+gk)
        af[1] = f2tf(odd ? t3 : t2);   // (gm+8, k=ni*8+gk)
        af[2] = f2tf(odd ? u1 : u0);   // (gm,   k=ni*8+gk+4)
        af[3] = f2tf(odd ? u3 : u2);   // (gm+8, k=ni*8+gk+4)
        #pragma unroll
        for (int nd = 0; nd < 4; nd++) {
            uint32_t bb[2] = {sv[(ni * 8 + gk    ) * AQ_ST + nd * 8 + gm],
                              sv[(ni * 8 + gk + 4) * AQ_ST + nd * 8 + gm]};
            mma_tf32(vacc[nd], af, bb);
        }
    }

    // store O -> g_ctx[b, n, h*32 + d]
    const size_t obase = (size_t)b * NTOK * DIMC + (size_t)h * HD;
    #pragma unroll
    for (int nd = 0; nd < 4; nd++) {
        int c = nd * 8 + gk * 2;
        *(float2*)&g_ctx[obase + (size_t)(rb + gm)     * DIMC + c] =
            make_float2(vacc[nd][0], vacc[nd][1]);
        *(float2*)&g_ctx[obase + (size_t)(rb + gm + 8) * DIMC + c] =
            make_float2(vacc[nd][2], vacc[nd][3]);
    }
}

// ---------------------------------------------------------------------------
// launch
// ---------------------------------------------------------------------------
extern "C" void kernel_launch(void* const* d_in, const int* in_sizes, int n_in,
                              void* d_out, int out_size)
{
    const float* x      = (const float*)d_in[0];
    const float* mask   = (const float*)d_in[1];
    const float* qkv_w  = (const float*)d_in[2];
    const float* qkv_b  = (const float*)d_in[3];
    const float* proj_w = (const float*)d_in[4];
    const float* proj_b = (const float*)d_in[5];
    const float* table  = (const float*)d_in[6];
    const int*   rel    = (const int*)d_in[7];
    float* out = (float*)d_out;

    // 0: bias expand
    bias_expand_kernel<<<(NH * NTOK2 + 255) / 256, 256>>>(table, rel);

    // 1: QKV GEMM (M=110592, N=1536) -> g_qkv
    gemm_tf32_kernel<0><<<864 * 24, 256>>>(x, qkv_w, qkv_b, nullptr, 1536);

    // 2: attention (flash-style, register scores)
    cudaFuncSetAttribute(attn_kernel, cudaFuncAttributeMaxDynamicSharedMemorySize, ATTN_SMEM);
    attn_kernel<<<B_TOT * NH, 288, ATTN_SMEM>>>(mask);

    // 3: proj GEMM (M=110592, N=512) -> out
    gemm_tf32_kernel<1><<<864 * 8, 256>>>(nullptr, proj_w, proj_b, out, 512);
}

// round 13
// speedup vs baseline: 1.9751x; 1.2497x over previous
#include <cuda_runtime.h>
#include <cstdint>

// ---------------------------------------------------------------------------
// WindowAttention3D: B=768, N=144, C=512, H=16, hd=32, NW=96
// Round 9: GEMMs rebuilt: 64x64 warp tiles (BM=256,BN=128), cp.async 4-stage
//          pipeline over pre-rounded tf32 operands. Attention = R6 flash.
// ---------------------------------------------------------------------------

#define B_TOT   768
#define NTOK    144
#define DIMC    512
#define NH      16
#define HD      32
#define NWIN    96
#define SCALE   0.17677669529663687f   // 1/sqrt(32)
#define NTOK2   (NTOK*NTOK)            // 20736
#define BHSTRIDE (NTOK*HD)             // 4608
#define MTOT    (B_TOT*NTOK)           // 110592

// Scratch (device globals; allocation-free rule)
__device__ float g_qkv[3u*768u*16u*144u*32u];   // [3][B][H][N][hd] (tf32 bits)
__device__ float g_ctx[768u*144u*512u];         // [B][N][C]        (tf32 bits)
__device__ float g_bias[16u*144u*144u];         // [H][N][N]        (fp32)
__device__ float g_xtf[110592u*512u];           // x as tf32 bits
__device__ float g_wqtf[1536u*512u];            // qkv_w as tf32 bits
__device__ float g_wptf[512u*512u];             // proj_w as tf32 bits

// ---------------------------------------------------------------------------
__device__ __forceinline__ uint32_t f2tf(float x) {
    uint32_t r;
    asm("cvt.rna.tf32.f32 %0, %1;" : "=r"(r) : "f"(x));
    return r;
}

__device__ __forceinline__ uint4 f2tf4(float4 v) {
    uint4 u;
    u.x = f2tf(v.x); u.y = f2tf(v.y); u.z = f2tf(v.z); u.w = f2tf(v.w);
    return u;
}

__device__ __forceinline__ void mma_tf32(float* c, const uint32_t* a, const uint32_t* b) {
    asm volatile(
        "mma.sync.aligned.m16n8k8.row.col.f32.tf32.tf32.f32 "
        "{%0,%1,%2,%3},{%4,%5,%6,%7},{%8,%9},{%0,%1,%2,%3};\n"
        : "+f"(c[0]), "+f"(c[1]), "+f"(c[2]), "+f"(c[3])
        : "r"(a[0]), "r"(a[1]), "r"(a[2]), "r"(a[3]), "r"(b[0]), "r"(b[1]));
}

__device__ __forceinline__ uint32_t smem_u32(const void* p) {
    uint32_t a;
    asm("{ .reg .u64 t; cvta.to.shared.u64 t, %1; cvt.u32.u64 %0, t; }" : "=r"(a) : "l"(p));
    return a;
}

__device__ __forceinline__ void cp16(uint32_t saddr, const void* g) {
    asm volatile("cp.async.cg.shared.global [%0], [%1], 16;" :: "r"(saddr), "l"(g));
}
#define CP_COMMIT() asm volatile("cp.async.commit_group;" ::: "memory")
#define CP_WAIT2()  asm volatile("cp.async.wait_group 2;"  ::: "memory")

// ---------------------------------------------------------------------------
// Kernel 0: expand relative position bias table -> g_bias[h][n][m]
// ---------------------------------------------------------------------------
__global__ __launch_bounds__(256) void bias_expand_kernel(
    const float* __restrict__ table, const int* __restrict__ rel)
{
    int i = blockIdx.x * 256 + threadIdx.x;
    const int total = NH * NTOK2;
    if (i >= total) return;
    int h  = i / NTOK2;
    int nm = i - h * NTOK2;
    g_bias[i] = table[rel[nm] * NH + h];
}

// ---------------------------------------------------------------------------
// Kernel 0b: fp32 -> tf32-rounded bits (float4 granular)
// ---------------------------------------------------------------------------
__global__ __launch_bounds__(256) void cvt_tf32_kernel(
    const float* __restrict__ in, float* __restrict__ out, int n4)
{
    int i = blockIdx.x * 256 + threadIdx.x;
    if (i >= n4) return;
    float4 v = ((const float4*)in)[i];
    ((uint4*)out)[i] = f2tf4(v);
}

// ---------------------------------------------------------------------------
// TF32 GEMM: Out[m,n] = sum_k A[m,k]*W[n,k] + bias[n]
// BM=256, BN=128, BK=16, 256 threads (8 warps, 4x2), warp tile 64x64.
// 4-stage cp.async pipeline; operands are pre-rounded tf32 bits.
// MODE 0: A=g_xtf, W=g_wqtf, N=1536, scatter tf32 bits to g_qkv.
// MODE 1: A=g_ctx, W=g_wptf, N=512, fp32 out.
// ---------------------------------------------------------------------------
#define BM 256
#define BN 128
#define BK 16
#define AST 20                    // smem row stride (words)
#define AW (BM*AST)               // 5120 words per A stage
#define BW (BN*AST)               // 2560 words per B stage
#define STAGES 4
#define KTILES (DIMC/BK)          // 32
#define GEMM_SMEM (STAGES*(AW+BW)*4)   // 122880 B

template <int MODE>
__global__ __launch_bounds__(256) void gemm_tc_kernel(
    const float* __restrict__ bias, float* __restrict__ Out)
{
    extern __shared__ uint32_t sh[];
    const uint32_t sbase = smem_u32(sh);

    const int nT = (MODE == 0) ? 12 : 4;
    const int m_tile = blockIdx.x / nT;
    const int n_tile = blockIdx.x - m_tile * nT;
    const int m0 = m_tile * BM, n0 = n_tile * BN;

    const int tid  = threadIdx.x;
    const int warp = tid >> 5, lane = tid & 31;
    const int wm = warp >> 1;     // 0..3 (64 rows each)
    const int wn = warp & 1;      // 0..1 (64 cols each)
    const int gm = lane >> 2, gk = lane & 3;

    const float* __restrict__ Aptr = (MODE == 0 ? g_xtf : g_ctx) + (size_t)m0 * DIMC;
    const float* __restrict__ Wptr = (MODE == 0 ? g_wqtf : g_wptf) + (size_t)n0 * DIMC;

    const int lr = tid >> 2;          // 0..63
    const int lc = (tid & 3) * 4;     // word chunk {0,4,8,12}
    const uint32_t a_sm0 = sbase;
    const uint32_t b_sm0 = sbase + STAGES * AW * 4;

    float acc[4][8][4];
    #pragma unroll
    for (int im = 0; im < 4; im++)
        #pragma unroll
        for (int in = 0; in < 8; in++)
            #pragma unroll
            for (int l = 0; l < 4; l++) acc[im][in][l] = 0.f;

    // --- issue one k-tile's copies ---
    auto issue = [&](int t) {
        const int st = t & (STAGES - 1);
        const int kf = t * BK;
        const uint32_t ab = a_sm0 + st * AW * 4;
        #pragma unroll
        for (int j = 0; j < 4; j++) {
            int r = lr + j * 64;
            cp16(ab + (r * AST + lc) * 4, Aptr + (size_t)r * DIMC + kf + lc);
        }
        const uint32_t bb = b_sm0 + st * BW * 4;
        #pragma unroll
        for (int j = 0; j < 2; j++) {
            int r = lr + j * 64;
            cp16(bb + (r * AST + lc) * 4, Wptr + (size_t)r * DIMC + kf + lc);
        }
    };

    issue(0); CP_COMMIT();
    issue(1); CP_COMMIT();
    issue(2); CP_COMMIT();

    for (int t = 0; t < KTILES; t++) {
        CP_WAIT2();
        __syncthreads();
        if (t + 3 < KTILES) issue(t + 3);
        CP_COMMIT();

        const int st = t & (STAGES - 1);
        const uint32_t* __restrict__ a_s = sh + st * AW;
        const uint32_t* __restrict__ b_s = sh + STAGES * AW + st * BW;

        #pragma unroll
        for (int kk = 0; kk < BK; kk += 8) {
            uint32_t afr[4][4], bfr[8][2];
            #pragma unroll
            for (int im = 0; im < 4; im++) {
                int rb = wm * 64 + im * 16;
                afr[im][0] = a_s[(rb + gm    ) * AST + kk + gk    ];
                afr[im][1] = a_s[(rb + gm + 8) * AST + kk + gk    ];
                afr[im][2] = a_s[(rb + gm    ) * AST + kk + gk + 4];
                afr[im][3] = a_s[(rb + gm + 8) * AST + kk + gk + 4];
            }
            #pragma unroll
            for (int in = 0; in < 8; in++) {
                int cb = wn * 64 + in * 8;
                bfr[in][0] = b_s[(cb + gm) * AST + kk + gk    ];
                bfr[in][1] = b_s[(cb + gm) * AST + kk + gk + 4];
            }
            #pragma unroll
            for (int im = 0; im < 4; im++)
                #pragma unroll
                for (int in = 0; in < 8; in++)
                    mma_tf32(acc[im][in], afr[im], bfr[in]);
        }
    }

    // epilogue: bias add + store/scatter
    #pragma unroll
    for (int im = 0; im < 4; im++) {
        #pragma unroll
        for (int half = 0; half < 2; half++) {
            int rg = m0 + wm * 64 + im * 16 + gm + half * 8;
            int b_idx = rg / NTOK;
            int ntk   = rg - b_idx * NTOK;
            #pragma unroll
            for (int in = 0; in < 8; in++) {
                int cg = n0 + wn * 64 + in * 8 + gk * 2;
                float v0 = acc[im][in][half * 2 + 0] + bias[cg];
                float v1 = acc[im][in][half * 2 + 1] + bias[cg + 1];
                if (MODE == 0) {
                    int which = cg >> 9;
                    int rem   = cg & 511;
                    int h     = rem >> 5;
                    int d     = rem & 31;
                    size_t dst = ((size_t)(which * B_TOT + b_idx) * NH + h) * BHSTRIDE
                               + (size_t)ntk * HD + d;
                    *(float2*)&g_qkv[dst] =
                        make_float2(__uint_as_float(f2tf(v0)), __uint_as_float(f2tf(v1)));
                } else {
                    *(float2*)&Out[(size_t)rg * DIMC + cg] = make_float2(v0, v1);
                }
            }
        }
    }
}

// ---------------------------------------------------------------------------
// Kernel 2: flash-style attention per (b,h). 288 threads (9 warps), each warp
// owns 16 rows; scores in registers; quad-shfl softmax; shfl C->A repack.
// q,k,v arrive as tf32 bits (no staging cvt); O stored as tf32 bits.
// ---------------------------------------------------------------------------
#define AQ_ST 36
#define ATTN_SMEM (3 * NTOK * AQ_ST * 4)   // 62208 B

__global__ __launch_bounds__(288, 1) void attn_kernel(const float* __restrict__ mask)
{
    extern __shared__ uint32_t sm[];
    uint32_t* sq = sm;
    uint32_t* sk = sq + NTOK * AQ_ST;
    uint32_t* sv = sk + NTOK * AQ_ST;

    const int bh = blockIdx.x;
    const int b  = bh >> 4, h = bh & 15;
    const int w  = b % NWIN;

    const int tid  = threadIdx.x;
    const int warp = tid >> 5, lane = tid & 31;
    const int gm = lane >> 2, gk = lane & 3;
    const int rb = warp * 16;

    const size_t qbase = ((size_t)(0 * B_TOT + b) * NH + h) * BHSTRIDE;
    const size_t kbase = ((size_t)(1 * B_TOT + b) * NH + h) * BHSTRIDE;
    const size_t vbase = ((size_t)(2 * B_TOT + b) * NH + h) * BHSTRIDE;

    // stage q,k,v [144][32] (already tf32 bits), padded stride 36
    for (int i = tid; i < (NTOK * HD / 4); i += 288) {
        int row = i >> 3;
        int d   = (i & 7) << 2;
        *(uint4*)&sq[row * AQ_ST + d] = *(const uint4*)&g_qkv[qbase + (size_t)row * HD + d];
        *(uint4*)&sk[row * AQ_ST + d] = *(const uint4*)&g_qkv[kbase + (size_t)row * HD + d];
        *(uint4*)&sv[row * AQ_ST + d] = *(const uint4*)&g_qkv[vbase + (size_t)row * HD + d];
    }
    __syncthreads();

    const float* __restrict__ biasp = g_bias + (size_t)h * NTOK2;
    const float* __restrict__ maskp = mask   + (size_t)w * NTOK2;

    // Q fragments (loaded once, reused for all 18 column tiles)
    uint32_t qf[4][4];
    #pragma unroll
    for (int k8 = 0; k8 < 4; k8++) {
        qf[k8][0] = sq[(rb + gm    ) * AQ_ST + k8 * 8 + gk    ];
        qf[k8][1] = sq[(rb + gm + 8) * AQ_ST + k8 * 8 + gk    ];
        qf[k8][2] = sq[(rb + gm    ) * AQ_ST + k8 * 8 + gk + 4];
        qf[k8][3] = sq[(rb + gm + 8) * AQ_ST + k8 * 8 + gk + 4];
    }

    // ---- S = scale*q@k^T + bias + mask in registers p[18][4] ----
    float p[18][4];
    #pragma unroll
    for (int ni = 0; ni < 18; ni++) {
        float acc[4] = {0.f, 0.f, 0.f, 0.f};
        #pragma unroll
        for (int k8 = 0; k8 < 4; k8++) {
            uint32_t bb[2] = {sk[(ni * 8 + gm) * AQ_ST + k8 * 8 + gk],
                              sk[(ni * 8 + gm) * AQ_ST + k8 * 8 + gk + 4]};
            mma_tf32(acc, qf[k8], bb);
        }
        int c = ni * 8 + gk * 2;
        float2 b0 = *(const float2*)&biasp[(rb + gm)     * NTOK + c];
        float2 b1 = *(const float2*)&biasp[(rb + gm + 8) * NTOK + c];
        float2 m0 = *(const float2*)&maskp[(rb + gm)     * NTOK + c];
        float2 m1 = *(const float2*)&maskp[(rb + gm + 8) * NTOK + c];
        p[ni][0] = acc[0] * SCALE + b0.x + m0.x;
        p[ni][1] = acc[1] * SCALE + b0.y + m0.y;
        p[ni][2] = acc[2] * SCALE + b1.x + m1.x;
        p[ni][3] = acc[3] * SCALE + b1.y + m1.y;
    }

    // ---- softmax in registers ----
    float mx0 = -1e30f, mx1 = -1e30f;
    #pragma unroll
    for (int ni = 0; ni < 18; ni++) {
        mx0 = fmaxf(mx0, fmaxf(p[ni][0], p[ni][1]));
        mx1 = fmaxf(mx1, fmaxf(p[ni][2], p[ni][3]));
    }
    mx0 = fmaxf(mx0, __shfl_xor_sync(0xffffffffu, mx0, 1));
    mx1 = fmaxf(mx1, __shfl_xor_sync(0xffffffffu, mx1, 1));
    mx0 = fmaxf(mx0, __shfl_xor_sync(0xffffffffu, mx0, 2));
    mx1 = fmaxf(mx1, __shfl_xor_sync(0xffffffffu, mx1, 2));

    float s0 = 0.f, s1 = 0.f;
    #pragma unroll
    for (int ni = 0; ni < 18; ni++) {
        p[ni][0] = __expf(p[ni][0] - mx0);
        p[ni][1] = __expf(p[ni][1] - mx0);
        p[ni][2] = __expf(p[ni][2] - mx1);
        p[ni][3] = __expf(p[ni][3] - mx1);
        s0 += p[ni][0] + p[ni][1];
        s1 += p[ni][2] + p[ni][3];
    }
    s0 += __shfl_xor_sync(0xffffffffu, s0, 1);
    s1 += __shfl_xor_sync(0xffffffffu, s1, 1);
    s0 += __shfl_xor_sync(0xffffffffu, s0, 2);
    s1 += __shfl_xor_sync(0xffffffffu, s1, 2);
    const float inv0 = 1.f / s0, inv1 = 1.f / s1;
    #pragma unroll
    for (int ni = 0; ni < 18; ni++) {
        p[ni][0] *= inv0; p[ni][1] *= inv0;
        p[ni][2] *= inv1; p[ni][3] *= inv1;
    }

    // ---- O = P @ v: quad-shfl repack C-frag -> A-frag, mma with v ----
    float vacc[4][4];
    #pragma unroll
    for (int nd = 0; nd < 4; nd++)
        #pragma unroll
        for (int l = 0; l < 4; l++) vacc[nd][l] = 0.f;

    const int base  = lane & ~3;
    const int src01 = base + (gk >> 1);
    const int src23 = src01 + 2;
    const bool odd  = (gk & 1);

    #pragma unroll
    for (int ni = 0; ni < 18; ni++) {
        float t0 = __shfl_sync(0xffffffffu, p[ni][0], src01);
        float t1 = __shfl_sync(0xffffffffu, p[ni][1], src01);
        float t2 = __shfl_sync(0xffffffffu, p[ni][2], src01);
        float t3 = __shfl_sync(0xffffffffu, p[ni][3], src01);
        float u0 = __shfl_sync(0xffffffffu, p[ni][0], src23);
        float u1 = __shfl_sync(0xffffffffu, p[ni][1], src23);
        float u2 = __shfl_sync(0xffffffffu, p[ni][2], src23);
        float u3 = __shfl_sync(0xffffffffu, p[ni][3], src23);
        uint32_t af[4];
        af[0] = f2tf(odd ? t1 : t0);
        af[1] = f2tf(odd ? t3 : t2);
        af[2] = f2tf(odd ? u1 : u0);
        af[3] = f2tf(odd ? u3 : u2);
        #pragma unroll
        for (int nd = 0; nd < 4; nd++) {
            uint32_t bb[2] = {sv[(ni * 8 + gk    ) * AQ_ST + nd * 8 + gm],
                              sv[(ni * 8 + gk + 4) * AQ_ST + nd * 8 + gm]};
            mma_tf32(vacc[nd], af, bb);
        }
    }

    // store O -> g_ctx[b, n, h*32 + d] as tf32 bits (consumed by proj GEMM)
    const size_t obase = (size_t)b * NTOK * DIMC + (size_t)h * HD;
    #pragma unroll
    for (int nd = 0; nd < 4; nd++) {
        int c = nd * 8 + gk * 2;
        *(float2*)&g_ctx[obase + (size_t)(rb + gm)     * DIMC + c] =
            make_float2(__uint_as_float(f2tf(vacc[nd][0])), __uint_as_float(f2tf(vacc[nd][1])));
        *(float2*)&g_ctx[obase + (size_t)(rb + gm + 8) * DIMC + c] =
            make_float2(__uint_as_float(f2tf(vacc[nd][2])), __uint_as_float(f2tf(vacc[nd][3])));
    }
}

// ---------------------------------------------------------------------------
// launch
// ---------------------------------------------------------------------------
extern "C" void kernel_launch(void* const* d_in, const int* in_sizes, int n_in,
                              void* d_out, int out_size)
{
    const float* x      = (const float*)d_in[0];
    const float* mask   = (const float*)d_in[1];
    const float* qkv_w  = (const float*)d_in[2];
    const float* qkv_b  = (const float*)d_in[3];
    const float* proj_w = (const float*)d_in[4];
    const float* proj_b = (const float*)d_in[5];
    const float* table  = (const float*)d_in[6];
    const int*   rel    = (const int*)d_in[7];
    float* out = (float*)d_out;

    float* d_xtf;  cudaGetSymbolAddress((void**)&d_xtf,  g_xtf);
    float* d_wqtf; cudaGetSymbolAddress((void**)&d_wqtf, g_wqtf);
    float* d_wptf; cudaGetSymbolAddress((void**)&d_wptf, g_wptf);

    // 0: bias expand + tf32 pre-rounding of x and weights
    bias_expand_kernel<<<(NH * NTOK2 + 255) / 256, 256>>>(table, rel);
    cvt_tf32_kernel<<<(MTOT * DIMC / 4 + 255) / 256, 256>>>(x, d_xtf, MTOT * DIMC / 4);
    cvt_tf32_kernel<<<(1536 * DIMC / 4 + 255) / 256, 256>>>(qkv_w, d_wqtf, 1536 * DIMC / 4);
    cvt_tf32_kernel<<<(DIMC * DIMC / 4 + 255) / 256, 256>>>(proj_w, d_wptf, DIMC * DIMC / 4);

    cudaFuncSetAttribute(gemm_tc_kernel<0>, cudaFuncAttributeMaxDynamicSharedMemorySize, GEMM_SMEM);
    cudaFuncSetAttribute(gemm_tc_kernel<1>, cudaFuncAttributeMaxDynamicSharedMemorySize, GEMM_SMEM);

    // 1: QKV GEMM (M=110592, N=1536) -> g_qkv (tf32 bits)
    gemm_tc_kernel<0><<<(MTOT / BM) * 12, 256, GEMM_SMEM>>>(qkv_b, nullptr);

    // 2: attention (flash-style, register scores)
    cudaFuncSetAttribute(attn_kernel, cudaFuncAttributeMaxDynamicSharedMemorySize, ATTN_SMEM);
    attn_kernel<<<B_TOT * NH, 288, ATTN_SMEM>>>(mask);

    // 3: proj GEMM (M=110592, N=512) -> out (fp32)
    gemm_tc_kernel<1><<<(MTOT / BM) * 4, 256, GEMM_SMEM>>>(proj_b, out);
}

// round 15
// speedup vs baseline: 2.1787x; 1.1031x over previous
#include <cuda_runtime.h>
#include <cstdint>

// ---------------------------------------------------------------------------
// WindowAttention3D: B=768, N=144, C=512, H=16, hd=32, NW=96
// Round 14: attention occupancy 2 CTAs/SM (launch_bounds 288,2) + normalization
//           folded into PV repack. GEMMs unchanged from R9.
// ---------------------------------------------------------------------------

#define B_TOT   768
#define NTOK    144
#define DIMC    512
#define NH      16
#define HD      32
#define NWIN    96
#define SCALE   0.17677669529663687f   // 1/sqrt(32)
#define NTOK2   (NTOK*NTOK)            // 20736
#define BHSTRIDE (NTOK*HD)             // 4608
#define MTOT    (B_TOT*NTOK)           // 110592

// Scratch (device globals; allocation-free rule)
__device__ float g_qkv[3u*768u*16u*144u*32u];   // [3][B][H][N][hd] (tf32 bits)
__device__ float g_ctx[768u*144u*512u];         // [B][N][C]        (tf32 bits)
__device__ float g_bias[16u*144u*144u];         // [H][N][N]        (fp32)
__device__ float g_xtf[110592u*512u];           // x as tf32 bits
__device__ float g_wqtf[1536u*512u];            // qkv_w as tf32 bits
__device__ float g_wptf[512u*512u];             // proj_w as tf32 bits

// ---------------------------------------------------------------------------
__device__ __forceinline__ uint32_t f2tf(float x) {
    uint32_t r;
    asm("cvt.rna.tf32.f32 %0, %1;" : "=r"(r) : "f"(x));
    return r;
}

__device__ __forceinline__ uint4 f2tf4(float4 v) {
    uint4 u;
    u.x = f2tf(v.x); u.y = f2tf(v.y); u.z = f2tf(v.z); u.w = f2tf(v.w);
    return u;
}

__device__ __forceinline__ void mma_tf32(float* c, const uint32_t* a, const uint32_t* b) {
    asm volatile(
        "mma.sync.aligned.m16n8k8.row.col.f32.tf32.tf32.f32 "
        "{%0,%1,%2,%3},{%4,%5,%6,%7},{%8,%9},{%0,%1,%2,%3};\n"
        : "+f"(c[0]), "+f"(c[1]), "+f"(c[2]), "+f"(c[3])
        : "r"(a[0]), "r"(a[1]), "r"(a[2]), "r"(a[3]), "r"(b[0]), "r"(b[1]));
}

__device__ __forceinline__ uint32_t smem_u32(const void* p) {
    uint32_t a;
    asm("{ .reg .u64 t; cvta.to.shared.u64 t, %1; cvt.u32.u64 %0, t; }" : "=r"(a) : "l"(p));
    return a;
}

__device__ __forceinline__ void cp16(uint32_t saddr, const void* g) {
    asm volatile("cp.async.cg.shared.global [%0], [%1], 16;" :: "r"(saddr), "l"(g));
}
#define CP_COMMIT() asm volatile("cp.async.commit_group;" ::: "memory")
#define CP_WAIT2()  asm volatile("cp.async.wait_group 2;"  ::: "memory")

// ---------------------------------------------------------------------------
// Kernel 0: expand relative position bias table -> g_bias[h][n][m]
// ---------------------------------------------------------------------------
__global__ __launch_bounds__(256) void bias_expand_kernel(
    const float* __restrict__ table, const int* __restrict__ rel)
{
    int i = blockIdx.x * 256 + threadIdx.x;
    const int total = NH * NTOK2;
    if (i >= total) return;
    int h  = i / NTOK2;
    int nm = i - h * NTOK2;
    g_bias[i] = table[rel[nm] * NH + h];
}

// ---------------------------------------------------------------------------
// Kernel 0b: fp32 -> tf32-rounded bits (float4 granular)
// ---------------------------------------------------------------------------
__global__ __launch_bounds__(256) void cvt_tf32_kernel(
    const float* __restrict__ in, float* __restrict__ out, int n4)
{
    int i = blockIdx.x * 256 + threadIdx.x;
    if (i >= n4) return;
    float4 v = ((const float4*)in)[i];
    ((uint4*)out)[i] = f2tf4(v);
}

// ---------------------------------------------------------------------------
// TF32 GEMM: Out[m,n] = sum_k A[m,k]*W[n,k] + bias[n]
// BM=256, BN=128, BK=16, 256 threads (8 warps, 4x2), warp tile 64x64.
// 4-stage cp.async pipeline; operands are pre-rounded tf32 bits. (= R9)
// ---------------------------------------------------------------------------
#define BM 256
#define BN 128
#define BK 16
#define AST 20
#define AW (BM*AST)
#define BW (BN*AST)
#define STAGES 4
#define KTILES (DIMC/BK)
#define GEMM_SMEM (STAGES*(AW+BW)*4)

template <int MODE>
__global__ __launch_bounds__(256) void gemm_tc_kernel(
    const float* __restrict__ bias, float* __restrict__ Out)
{
    extern __shared__ uint32_t sh[];
    const uint32_t sbase = smem_u32(sh);

    const int nT = (MODE == 0) ? 12 : 4;
    const int m_tile = blockIdx.x / nT;
    const int n_tile = blockIdx.x - m_tile * nT;
    const int m0 = m_tile * BM, n0 = n_tile * BN;

    const int tid  = threadIdx.x;
    const int warp = tid >> 5, lane = tid & 31;
    const int wm = warp >> 1;
    const int wn = warp & 1;
    const int gm = lane >> 2, gk = lane & 3;

    const float* __restrict__ Aptr = (MODE == 0 ? g_xtf : g_ctx) + (size_t)m0 * DIMC;
    const float* __restrict__ Wptr = (MODE == 0 ? g_wqtf : g_wptf) + (size_t)n0 * DIMC;

    const int lr = tid >> 2;
    const int lc = (tid & 3) * 4;
    const uint32_t a_sm0 = sbase;
    const uint32_t b_sm0 = sbase + STAGES * AW * 4;

    float acc[4][8][4];
    #pragma unroll
    for (int im = 0; im < 4; im++)
        #pragma unroll
        for (int in = 0; in < 8; in++)
            #pragma unroll
            for (int l = 0; l < 4; l++) acc[im][in][l] = 0.f;

    auto issue = [&](int t) {
        const int st = t & (STAGES - 1);
        const int kf = t * BK;
        const uint32_t ab = a_sm0 + st * AW * 4;
        #pragma unroll
        for (int j = 0; j < 4; j++) {
            int r = lr + j * 64;
            cp16(ab + (r * AST + lc) * 4, Aptr + (size_t)r * DIMC + kf + lc);
        }
        const uint32_t bb = b_sm0 + st * BW * 4;
        #pragma unroll
        for (int j = 0; j < 2; j++) {
            int r = lr + j * 64;
            cp16(bb + (r * AST + lc) * 4, Wptr + (size_t)r * DIMC + kf + lc);
        }
    };

    issue(0); CP_COMMIT();
    issue(1); CP_COMMIT();
    issue(2); CP_COMMIT();

    for (int t = 0; t < KTILES; t++) {
        CP_WAIT2();
        __syncthreads();
        if (t + 3 < KTILES) issue(t + 3);
        CP_COMMIT();

        const int st = t & (STAGES - 1);
        const uint32_t* __restrict__ a_s = sh + st * AW;
        const uint32_t* __restrict__ b_s = sh + STAGES * AW + st * BW;

        #pragma unroll
        for (int kk = 0; kk < BK; kk += 8) {
            uint32_t afr[4][4], bfr[8][2];
            #pragma unroll
            for (int im = 0; im < 4; im++) {
                int rb = wm * 64 + im * 16;
                afr[im][0] = a_s[(rb + gm    ) * AST + kk + gk    ];
                afr[im][1] = a_s[(rb + gm + 8) * AST + kk + gk    ];
                afr[im][2] = a_s[(rb + gm    ) * AST + kk + gk + 4];
                afr[im][3] = a_s[(rb + gm + 8) * AST + kk + gk + 4];
            }
            #pragma unroll
            for (int in = 0; in < 8; in++) {
                int cb = wn * 64 + in * 8;
                bfr[in][0] = b_s[(cb + gm) * AST + kk + gk    ];
                bfr[in][1] = b_s[(cb + gm) * AST + kk + gk + 4];
            }
            #pragma unroll
            for (int im = 0; im < 4; im++)
                #pragma unroll
                for (int in = 0; in < 8; in++)
                    mma_tf32(acc[im][in], afr[im], bfr[in]);
        }
    }

    #pragma unroll
    for (int im = 0; im < 4; im++) {
        #pragma unroll
        for (int half = 0; half < 2; half++) {
            int rg = m0 + wm * 64 + im * 16 + gm + half * 8;
            int b_idx = rg / NTOK;
            int ntk   = rg - b_idx * NTOK;
            #pragma unroll
            for (int in = 0; in < 8; in++) {
                int cg = n0 + wn * 64 + in * 8 + gk * 2;
                float v0 = acc[im][in][half * 2 + 0] + bias[cg];
                float v1 = acc[im][in][half * 2 + 1] + bias[cg + 1];
                if (MODE == 0) {
                    int which = cg >> 9;
                    int rem   = cg & 511;
                    int h     = rem >> 5;
                    int d     = rem & 31;
                    size_t dst = ((size_t)(which * B_TOT + b_idx) * NH + h) * BHSTRIDE
                               + (size_t)ntk * HD + d;
                    *(float2*)&g_qkv[dst] =
                        make_float2(__uint_as_float(f2tf(v0)), __uint_as_float(f2tf(v1)));
                } else {
                    *(float2*)&Out[(size_t)rg * DIMC + cg] = make_float2(v0, v1);
                }
            }
        }
    }
}

// ---------------------------------------------------------------------------
// Kernel 2: flash-style attention per (b,h). 288 threads (9 warps), 16 rows
// per warp; scores in registers; quad-shfl softmax; shfl C->A repack with
// normalization folded in. Target 2 CTAs/SM.
// ---------------------------------------------------------------------------
#define AQ_ST 36
#define ATTN_SMEM (3 * NTOK * AQ_ST * 4)   // 62208 B

__global__ __launch_bounds__(288, 2) void attn_kernel(const float* __restrict__ mask)
{
    extern __shared__ uint32_t sm[];
    uint32_t* sq = sm;
    uint32_t* sk = sq + NTOK * AQ_ST;
    uint32_t* sv = sk + NTOK * AQ_ST;

    const int bh = blockIdx.x;
    const int b  = bh >> 4, h = bh & 15;
    const int w  = b % NWIN;

    const int tid  = threadIdx.x;
    const int warp = tid >> 5, lane = tid & 31;
    const int gm = lane >> 2, gk = lane & 3;
    const int rb = warp * 16;

    const size_t qbase = ((size_t)(0 * B_TOT + b) * NH + h) * BHSTRIDE;
    const size_t kbase = ((size_t)(1 * B_TOT + b) * NH + h) * BHSTRIDE;
    const size_t vbase = ((size_t)(2 * B_TOT + b) * NH + h) * BHSTRIDE;

    // stage q,k,v [144][32] (already tf32 bits), padded stride 36
    for (int i = tid; i < (NTOK * HD / 4); i += 288) {
        int row = i >> 3;
        int d   = (i & 7) << 2;
        *(uint4*)&sq[row * AQ_ST + d] = *(const uint4*)&g_qkv[qbase + (size_t)row * HD + d];
        *(uint4*)&sk[row * AQ_ST + d] = *(const uint4*)&g_qkv[kbase + (size_t)row * HD + d];
        *(uint4*)&sv[row * AQ_ST + d] = *(const uint4*)&g_qkv[vbase + (size_t)row * HD + d];
    }
    __syncthreads();

    const float* __restrict__ biasp = g_bias + (size_t)h * NTOK2;
    const float* __restrict__ maskp = mask   + (size_t)w * NTOK2;

    // Q fragments (loaded once, reused for all 18 column tiles)
    uint32_t qf[4][4];
    #pragma unroll
    for (int k8 = 0; k8 < 4; k8++) {
        qf[k8][0] = sq[(rb + gm    ) * AQ_ST + k8 * 8 + gk    ];
        qf[k8][1] = sq[(rb + gm + 8) * AQ_ST + k8 * 8 + gk    ];
        qf[k8][2] = sq[(rb + gm    ) * AQ_ST + k8 * 8 + gk + 4];
        qf[k8][3] = sq[(rb + gm + 8) * AQ_ST + k8 * 8 + gk + 4];
    }

    // ---- S = scale*q@k^T + bias + mask in registers p[18][4] ----
    float p[18][4];
    #pragma unroll
    for (int ni = 0; ni < 18; ni++) {
        float acc[4] = {0.f, 0.f, 0.f, 0.f};
        #pragma unroll
        for (int k8 = 0; k8 < 4; k8++) {
            uint32_t bb[2] = {sk[(ni * 8 + gm) * AQ_ST + k8 * 8 + gk],
                              sk[(ni * 8 + gm) * AQ_ST + k8 * 8 + gk + 4]};
            mma_tf32(acc, qf[k8], bb);
        }
        int c = ni * 8 + gk * 2;
        float2 b0 = *(const float2*)&biasp[(rb + gm)     * NTOK + c];
        float2 b1 = *(const float2*)&biasp[(rb + gm + 8) * NTOK + c];
        float2 m0 = *(const float2*)&maskp[(rb + gm)     * NTOK + c];
        float2 m1 = *(const float2*)&maskp[(rb + gm + 8) * NTOK + c];
        p[ni][0] = acc[0] * SCALE + b0.x + m0.x;
        p[ni][1] = acc[1] * SCALE + b0.y + m0.y;
        p[ni][2] = acc[2] * SCALE + b1.x + m1.x;
        p[ni][3] = acc[3] * SCALE + b1.y + m1.y;
    }

    // ---- softmax in registers (normalization deferred to repack) ----
    float mx0 = -1e30f, mx1 = -1e30f;
    #pragma unroll
    for (int ni = 0; ni < 18; ni++) {
        mx0 = fmaxf(mx0, fmaxf(p[ni][0], p[ni][1]));
        mx1 = fmaxf(mx1, fmaxf(p[ni][2], p[ni][3]));
    }
    mx0 = fmaxf(mx0, __shfl_xor_sync(0xffffffffu, mx0, 1));
    mx1 = fmaxf(mx1, __shfl_xor_sync(0xffffffffu, mx1, 1));
    mx0 = fmaxf(mx0, __shfl_xor_sync(0xffffffffu, mx0, 2));
    mx1 = fmaxf(mx1, __shfl_xor_sync(0xffffffffu, mx1, 2));

    float s0 = 0.f, s1 = 0.f;
    #pragma unroll
    for (int ni = 0; ni < 18; ni++) {
        p[ni][0] = __expf(p[ni][0] - mx0);
        p[ni][1] = __expf(p[ni][1] - mx0);
        p[ni][2] = __expf(p[ni][2] - mx1);
        p[ni][3] = __expf(p[ni][3] - mx1);
        s0 += p[ni][0] + p[ni][1];
        s1 += p[ni][2] + p[ni][3];
    }
    s0 += __shfl_xor_sync(0xffffffffu, s0, 1);
    s1 += __shfl_xor_sync(0xffffffffu, s1, 1);
    s0 += __shfl_xor_sync(0xffffffffu, s0, 2);
    s1 += __shfl_xor_sync(0xffffffffu, s1, 2);
    const float inv0 = 1.f / s0, inv1 = 1.f / s1;

    // ---- O = P @ v: quad-shfl repack C->A frag (x inv fused), mma with v ----
    float vacc[4][4];
    #pragma unroll
    for (int nd = 0; nd < 4; nd++)
        #pragma unroll
        for (int l = 0; l < 4; l++) vacc[nd][l] = 0.f;

    const int base  = lane & ~3;
    const int src01 = base + (gk >> 1);
    const int src23 = src01 + 2;
    const bool odd  = (gk & 1);

    #pragma unroll
    for (int ni = 0; ni < 18; ni++) {
        float t0 = __shfl_sync(0xffffffffu, p[ni][0], src01);
        float t1 = __shfl_sync(0xffffffffu, p[ni][1], src01);
        float t2 = __shfl_sync(0xffffffffu, p[ni][2], src01);
        float t3 = __shfl_sync(0xffffffffu, p[ni][3], src01);
        float u0 = __shfl_sync(0xffffffffu, p[ni][0], src23);
        float u1 = __shfl_sync(0xffffffffu, p[ni][1], src23);
        float u2 = __shfl_sync(0xffffffffu, p[ni][2], src23);
        float u3 = __shfl_sync(0xffffffffu, p[ni][3], src23);
        uint32_t af[4];
        af[0] = f2tf((odd ? t1 : t0) * inv0);   // row gm
        af[1] = f2tf((odd ? t3 : t2) * inv1);   // row gm+8
        af[2] = f2tf((odd ? u1 : u0) * inv0);   // row gm
        af[3] = f2tf((odd ? u3 : u2) * inv1);   // row gm+8
        #pragma unroll
        for (int nd = 0; nd < 4; nd++) {
            uint32_t bb[2] = {sv[(ni * 8 + gk    ) * AQ_ST + nd * 8 + gm],
                              sv[(ni * 8 + gk + 4) * AQ_ST + nd * 8 + gm]};
            mma_tf32(vacc[nd], af, bb);
        }
    }

    // store O -> g_ctx[b, n, h*32 + d] as tf32 bits (consumed by proj GEMM)
    const size_t obase = (size_t)b * NTOK * DIMC + (size_t)h * HD;
    #pragma unroll
    for (int nd = 0; nd < 4; nd++) {
        int c = nd * 8 + gk * 2;
        *(float2*)&g_ctx[obase + (size_t)(rb + gm)     * DIMC + c] =
            make_float2(__uint_as_float(f2tf(vacc[nd][0])), __uint_as_float(f2tf(vacc[nd][1])));
        *(float2*)&g_ctx[obase + (size_t)(rb + gm + 8) * DIMC + c] =
            make_float2(__uint_as_float(f2tf(vacc[nd][2])), __uint_as_float(f2tf(vacc[nd][3])));
    }
}

// ---------------------------------------------------------------------------
// launch
// ---------------------------------------------------------------------------
extern "C" void kernel_launch(void* const* d_in, const int* in_sizes, int n_in,
                              void* d_out, int out_size)
{
    const float* x      = (const float*)d_in[0];
    const float* mask   = (const float*)d_in[1];
    const float* qkv_w  = (const float*)d_in[2];
    const float* qkv_b  = (const float*)d_in[3];
    const float* proj_w = (const float*)d_in[4];
    const float* proj_b = (const float*)d_in[5];
    const float* table  = (const float*)d_in[6];
    const int*   rel    = (const int*)d_in[7];
    float* out = (float*)d_out;

    float* d_xtf;  cudaGetSymbolAddress((void**)&d_xtf,  g_xtf);
    float* d_wqtf; cudaGetSymbolAddress((void**)&d_wqtf, g_wqtf);
    float* d_wptf; cudaGetSymbolAddress((void**)&d_wptf, g_wptf);

    // 0: bias expand + tf32 pre-rounding of x and weights
    bias_expand_kernel<<<(NH * NTOK2 + 255) / 256, 256>>>(table, rel);
    cvt_tf32_kernel<<<(MTOT * DIMC / 4 + 255) / 256, 256>>>(x, d_xtf, MTOT * DIMC / 4);
    cvt_tf32_kernel<<<(1536 * DIMC / 4 + 255) / 256, 256>>>(qkv_w, d_wqtf, 1536 * DIMC / 4);
    cvt_tf32_kernel<<<(DIMC * DIMC / 4 + 255) / 256, 256>>>(proj_w, d_wptf, DIMC * DIMC / 4);

    cudaFuncSetAttribute(gemm_tc_kernel<0>, cudaFuncAttributeMaxDynamicSharedMemorySize, GEMM_SMEM);
    cudaFuncSetAttribute(gemm_tc_kernel<1>, cudaFuncAttributeMaxDynamicSharedMemorySize, GEMM_SMEM);

    // 1: QKV GEMM (M=110592, N=1536) -> g_qkv (tf32 bits)
    gemm_tc_kernel<0><<<(MTOT / BM) * 12, 256, GEMM_SMEM>>>(qkv_b, nullptr);

    // 2: attention (flash-style, register scores, 2 CTAs/SM)
    cudaFuncSetAttribute(attn_kernel, cudaFuncAttributeMaxDynamicSharedMemorySize, ATTN_SMEM);
    attn_kernel<<<B_TOT * NH, 288, ATTN_SMEM>>>(mask);

    // 3: proj GEMM (M=110592, N=512) -> out (fp32)
    gemm_tc_kernel<1><<<(MTOT / BM) * 4, 256, GEMM_SMEM>>>(proj_b, out);
}